// round 12
// baseline (speedup 1.0000x reference)
#include <cuda_runtime.h>
#include <cstdint>

#define N_PATHS 65536
#define N_STEPS 512

// piecewise-cubic lambda table: 32 segments per step, 4 nodes per segment
#define NSEG    32
#define TILE    16

#define TPB1    64      // phase-1: one step per block (64 node-pairs)
#define TPB2    64
#define WARPS2  (TPB2/32)

// ---- constants (match reference float32 semantics) ----
#define DT_F        (1.0f/252.0f)
#define SQRT_DT_F   0.06299407883487120f     // sqrt(1/252)
#define KAPPA_F     2.72f
#define THETA_F     (-3.5f)
#define SIGMA_P_F   0.85f
#define RHO_F       (-0.85f)
#define CS_F        (0.5267826876426369f * 0.06299407883487120f) // sqrt(1-rho^2)*sqrt_dt
#define R_F         0.0373f
#define LAMBDA_MAX_F 3.0f
#define LOG_V_MIN_F (-7.0f)
#define LOG_V_MAX_F 2.0f
#define INV_NSTEPS  (1.0f/512.0f)
#define SEG_H       ((LOG_V_MAX_F - LOG_V_MIN_F) / (float)NSEG)      // 9/32
#define SEG_SCALE   ((float)NSEG / (LOG_V_MAX_F - LOG_V_MIN_F))      // 32/9
#define SEG_OFS     (-(LOG_V_MIN_F) * SEG_SCALE)
// drift restructure: lv + kappa*(theta-lv)*dt = A*lv + B
#define DRIFT_A     (1.0f - KAPPA_F * DT_F)
#define DRIFT_B     (KAPPA_F * THETA_F * DT_F)
#define NEG_SGDT    (-(SIGMA_P_F * DT_F))

// scratch (device global = legal scratch)
__device__ float4 g_coef[N_STEPS * NSEG];         // monomial cubic coeffs per segment

typedef unsigned long long ull;

// ---- packed f32x2 helpers (Blackwell fma.rn.f32x2) ----
__device__ __forceinline__ ull pack2(float a, float b) {
    ull r; asm("mov.b64 %0, {%1, %2};" : "=l"(r) : "f"(a), "f"(b)); return r;
}
__device__ __forceinline__ void unpack2(ull v, float& a, float& b) {
    asm("mov.b64 {%0, %1}, %2;" : "=f"(a), "=f"(b) : "l"(v));
}
__device__ __forceinline__ ull fma2(ull a, ull b, ull c) {
    ull d; asm("fma.rn.f32x2 %0, %1, %2, %3;" : "=l"(d) : "l"(a), "l"(b), "l"(c)); return d;
}
__device__ __forceinline__ ull mul2(ull a, ull b) {
    ull d; asm("mul.rn.f32x2 %0, %1, %2;" : "=l"(d) : "l"(a), "l"(b)); return d;
}

__device__ __forceinline__ float fast_tanh(float x) {
    float y;
    asm("tanh.approx.f32 %0, %1;" : "=f"(y) : "f"(x));
    return y;
}

// 5-op gelu on a pair (validated): gelu(x)=fma(0.5x, tanh(u), 0.5x)
__device__ __forceinline__ ull gelu2(ull x, ull GA, ull GB, ull GH) {
    ull x2 = mul2(x, x);
    ull u  = mul2(x, fma2(GA, x2, GB));
    ull hx = mul2(GH, x);
    float ulo, uhi; unpack2(u, ulo, uhi);
    ull tp = pack2(fast_tanh(ulo), fast_tanh(uhi));
    return fma2(hx, tp, hx);
}

// ---- cp.async helpers (LDGSTS) ----
__device__ __forceinline__ void cp_async16(void* smem_dst, const void* gmem_src) {
    uint32_t sa = (uint32_t)__cvta_generic_to_shared(smem_dst);
    asm volatile("cp.async.ca.shared.global [%0], [%1], 16;" :: "r"(sa), "l"(gmem_src) : "memory");
}
__device__ __forceinline__ void cp_async_commit() {
    asm volatile("cp.async.commit_group;" ::: "memory");
}

// ============================================================================
// Phase 1 (fused): lambda at segment nodes + cubic coefficients.
// One block = one time step. Thread tt (0..63): segment j = tt>>1, parity
// p = tt&1; pair-MLP lanes = nodes u = p/3 and u = p/3 + 2/3 of segment j.
// shfl_xor(1) assembles all 4 node values; even lanes emit the coeff float4.
// ============================================================================
__global__ __launch_bounds__(TPB1, 8)
void node_kernel(const float* __restrict__ W1,  const float* __restrict__ b1,
                 const float* __restrict__ W2,  const float* __restrict__ b2,
                 const float* __restrict__ W3,  const float* __restrict__ b3)
{
    __shared__ float sw1t[32], sb1[32];
    __shared__ ull   sw0d[32], sb2d[32], sw3d[32];
    __shared__ __align__(16) float sW2[1024];
    __shared__ float sb3s;

    const int tid = threadIdx.x;
    for (int i = tid; i < 1024; i += TPB1) sW2[i] = W2[i];
    if (tid < 32) {
        float w0 = W1[2 * tid];
        sw0d[tid] = pack2(w0, w0);
        sw1t[tid] = W1[2 * tid + 1];
        sb1[tid]  = b1[tid];
        float bb = b2[tid];
        sb2d[tid] = pack2(bb, bb);
        float w3 = W3[tid];
        sw3d[tid] = pack2(w3, w3);
    }
    if (tid == 0) sb3s = b3[0];
    __syncthreads();

    const float4* W2v = reinterpret_cast<const float4*>(sW2);
    const ull GA = pack2(0.0356774081363059f, 0.0356774081363059f);
    const ull GB = pack2(0.7978845608028654f, 0.7978845608028654f);
    const ull GH = pack2(0.5f, 0.5f);

    const int s = blockIdx.x;                 // time step
    const int j = tid >> 1;                   // segment 0..31
    const int p = tid & 1;                    // node parity
    const float t = (float)s * INV_NSTEPS;

    // lane A: u = p/3 ; lane B: u = p/3 + 2/3  (of segment j)
    const float lvA = fmaf((float)j + (float)p * 0.3333333333f, SEG_H, LOG_V_MIN_F);
    const float lvB = lvA + 0.6666666666f * SEG_H;
    const ull lvp = pack2(lvA, lvB);

    ull h1[32];
    #pragma unroll
    for (int k = 0; k < 32; k++) {
        float c1 = fmaf(sw1t[k], t, sb1[k]);
        ull arg = fma2(sw0d[k], lvp, pack2(c1, c1));
        h1[k] = gelu2(arg, GA, GB, GH);
    }

    ull red0 = pack2(0.0f, 0.0f);
    ull red1 = pack2(0.0f, 0.0f);
    #pragma unroll 1
    for (int jg = 0; jg < 8; jg++) {
        const int j0 = jg * 4;
        ull a0 = sb2d[j0 + 0];
        ull a1 = sb2d[j0 + 1];
        ull a2 = sb2d[j0 + 2];
        ull a3 = sb2d[j0 + 3];
        #pragma unroll
        for (int k4 = 0; k4 < 8; k4++) {
            ull h0 = h1[4 * k4 + 0];
            ull hA = h1[4 * k4 + 1];
            ull hB = h1[4 * k4 + 2];
            ull hC = h1[4 * k4 + 3];
            float4 q0 = W2v[(j0 + 0) * 8 + k4];
            float4 q1 = W2v[(j0 + 1) * 8 + k4];
            float4 q2 = W2v[(j0 + 2) * 8 + k4];
            float4 q3 = W2v[(j0 + 3) * 8 + k4];
            a0 = fma2(pack2(q0.x, q0.x), h0, a0);
            a0 = fma2(pack2(q0.y, q0.y), hA, a0);
            a0 = fma2(pack2(q0.z, q0.z), hB, a0);
            a0 = fma2(pack2(q0.w, q0.w), hC, a0);
            a1 = fma2(pack2(q1.x, q1.x), h0, a1);
            a1 = fma2(pack2(q1.y, q1.y), hA, a1);
            a1 = fma2(pack2(q1.z, q1.z), hB, a1);
            a1 = fma2(pack2(q1.w, q1.w), hC, a1);
            a2 = fma2(pack2(q2.x, q2.x), h0, a2);
            a2 = fma2(pack2(q2.y, q2.y), hA, a2);
            a2 = fma2(pack2(q2.z, q2.z), hB, a2);
            a2 = fma2(pack2(q2.w, q2.w), hC, a2);
            a3 = fma2(pack2(q3.x, q3.x), h0, a3);
            a3 = fma2(pack2(q3.y, q3.y), hA, a3);
            a3 = fma2(pack2(q3.z, q3.z), hB, a3);
            a3 = fma2(pack2(q3.w, q3.w), hC, a3);
        }
        red0 = fma2(sw3d[j0 + 0], gelu2(a0, GA, GB, GH), red0);
        red1 = fma2(sw3d[j0 + 1], gelu2(a1, GA, GB, GH), red1);
        red0 = fma2(sw3d[j0 + 2], gelu2(a2, GA, GB, GH), red0);
        red1 = fma2(sw3d[j0 + 3], gelu2(a3, GA, GB, GH), red1);
    }
    float rA0, rB0, rA1, rB1;
    unpack2(red0, rA0, rB0);
    unpack2(red1, rA1, rB1);
    float lamA = LAMBDA_MAX_F * tanhf((rA0 + rA1) + sb3s);   // u = p/3
    float lamB = LAMBDA_MAX_F * tanhf((rB0 + rB1) + sb3s);   // u = p/3 + 2/3

    // assemble the segment's 4 node values: f(0), f(1/3), f(2/3), f(1)
    float oA = __shfl_xor_sync(0xffffffffu, lamA, 1);
    float oB = __shfl_xor_sync(0xffffffffu, lamB, 1);
    if (p == 0) {
        float f0 = lamA, f2 = lamB;   // own: u = 0, 2/3
        float f1 = oA,   f3 = oB;     // partner: u = 1/3, 1
        float4 c;
        c.x = f0;
        c.y = 0.5f * (-11.0f * f0 + 18.0f * f1 - 9.0f  * f2 + 2.0f * f3);
        c.z = 0.5f * ( 18.0f * f0 - 45.0f * f1 + 36.0f * f2 - 9.0f * f3);
        c.w = 0.5f * ( -9.0f * f0 + 27.0f * f1 - 27.0f * f2 + 9.0f * f3);
        g_coef[s * NSEG + j] = c;
    }
}

// ============================================================================
// Phase 2: SDE sweep. Register double-buffered z staging (R10), cp.async
// double-buffered coeff tile (new): tile i+1's coefs stream during tile i's
// step loop — no exposed refill latency anywhere in the tile cycle.
// ============================================================================
__global__ __launch_bounds__(TPB2, 8)
void sde_kernel(const float* __restrict__ z1, const float* __restrict__ z2,
                const float* __restrict__ init_log_v,
                float* __restrict__ out)
{
    __shared__ float sza[WARPS2][32][TILE + 1];   // z1 in -> log_v out
    __shared__ float szb[WARPS2][32][TILE + 1];   // z2 in -> spot  out
    __shared__ __align__(16) float4 scoef[2][TILE][NSEG];   // 2 x 8 KB coeff tiles

    const int tid = threadIdx.x;
    const int w = tid >> 5;
    const int l = tid & 31;
    const int pbase = blockIdx.x * TPB2 + w * 32;

    const float* z1w = z1 + (size_t)pbase * N_STEPS;
    const float* z2w = z2 + (size_t)pbase * N_STEPS;
    float* out_lv = out;
    float* out_sp = out + (size_t)N_PATHS * N_STEPS;
    float* out_lq = out + 2 * (size_t)N_PATHS * N_STEPS;

    float lv  = init_log_v[0];
    float ls  = 0.0f;
    float lsq = 0.0f;

    const int pl_lo = (l >> 2);        // 0..7
    const int so    = (l & 3) * 4;     // 0,4,8,12

    // ---- initial prefetches (tile 0): z into regs, coef via cp.async ----
    float4 r1[4], r2[4];
    #pragma unroll
    for (int it = 0; it < 4; it++) {
        int pl = it * 8 + pl_lo;
        r1[it] = *reinterpret_cast<const float4*>(z1w + (size_t)pl * N_STEPS + so);
        r2[it] = *reinterpret_cast<const float4*>(z2w + (size_t)pl * N_STEPS + so);
    }
    {
        const float4* src = g_coef;                          // tile 0
        float4* dst = &scoef[0][0][0];
        #pragma unroll
        for (int i = 0; i < (TILE * NSEG) / TPB2; i++)       // 8 per thread
            cp_async16(dst + tid + i * TPB2, src + tid + i * TPB2);
        cp_async_commit();
    }

    #pragma unroll 1
    for (int s0 = 0; s0 < N_STEPS; s0 += TILE) {
        const int buf = (s0 / TILE) & 1;
        __syncthreads();   // previous tile's smem reads complete

        // ---- deposit prefetched z into padded smem ----
        #pragma unroll
        for (int it = 0; it < 4; it++) {
            int pl = it * 8 + pl_lo;
            sza[w][pl][so]     = r1[it].x; sza[w][pl][so + 1] = r1[it].y;
            sza[w][pl][so + 2] = r1[it].z; sza[w][pl][so + 3] = r1[it].w;
            szb[w][pl][so]     = r2[it].x; szb[w][pl][so + 1] = r2[it].y;
            szb[w][pl][so + 2] = r2[it].z; szb[w][pl][so + 3] = r2[it].w;
        }

        // ---- issue NEXT tile's prefetches (latency hidden under step loop) ----
        if (s0 + TILE < N_STEPS) {
            {
                const float4* src = g_coef + (size_t)(s0 + TILE) * NSEG;
                float4* dst = &scoef[buf ^ 1][0][0];
                #pragma unroll
                for (int i = 0; i < (TILE * NSEG) / TPB2; i++)
                    cp_async16(dst + tid + i * TPB2, src + tid + i * TPB2);
                cp_async_commit();
            }
            #pragma unroll
            for (int it = 0; it < 4; it++) {
                int pl = it * 8 + pl_lo;
                r1[it] = *reinterpret_cast<const float4*>(z1w + (size_t)pl * N_STEPS + s0 + TILE + so);
                r2[it] = *reinterpret_cast<const float4*>(z2w + (size_t)pl * N_STEPS + s0 + TILE + so);
            }
            asm volatile("cp.async.wait_group 1;" ::: "memory");   // this tile's coef done
        } else {
            asm volatile("cp.async.wait_group 0;" ::: "memory");
        }
        __syncthreads();   // z deposit + coef tile visible to all

        // ---- 16 sequential SDE steps (fully unrolled) ----
        #pragma unroll
        for (int si = 0; si < TILE; si++) {
            // off-chain pieces (z known at tile start)
            float z1s = sza[w][l][si];
            float z2s = szb[w][l][si];
            float dwv = SQRT_DT_F * z1s;
            float dws = fmaf(RHO_F, dwv, CS_F * z2s);
            float e    = fmaf(SIGMA_P_F, dwv, DRIFT_B);
            float base = fmaf(DRIFT_A, lv, e);

            // lambda chain: fma -> F2I.RD -> clamp -> LDS.128 -> Horner
            float x  = fmaf(lv, SEG_SCALE, SEG_OFS);      // [0, 32]
            int   j  = __float2int_rd(x);
            j = max(min(j, NSEG - 1), 0);
            float u  = x - (float)j;
            float4 c = scoef[buf][si][j];
            float lam = fmaf(fmaf(fmaf(c.w, u, c.z), u, c.y), u, c.x);

            float lv_next = fmaf(lam, NEG_SGDT, base);
            lv_next = fminf(fmaxf(lv_next, LOG_V_MIN_F), LOG_V_MAX_F);

            // lv >= -7 => exp(lv) >= 9e-4 >> 1e-10: vol = exp(lv/2), ev = vol^2
            float vol = __expf(0.5f * lv);
            float ev  = vol * vol;
            float ls_next = fmaf(vol, dws, fmaf(ev, -0.5f * DT_F, ls + R_F * DT_F));

            lsq = fmaf(lam * lam, DT_F, lsq);

            sza[w][l][si] = lv_next;
            szb[w][l][si] = __expf(ls_next);

            lv = lv_next;
            ls = ls_next;
        }
        __syncwarp();   // own-warp sza/szb writes visible before flush

        // ---- flush outputs (padded smem -> coalesced STG.128) ----
        #pragma unroll
        for (int it = 0; it < 4; it++) {
            int pl = it * 8 + pl_lo;
            float4 ov, os;
            ov.x = sza[w][pl][so];     ov.y = sza[w][pl][so + 1];
            ov.z = sza[w][pl][so + 2]; ov.w = sza[w][pl][so + 3];
            os.x = szb[w][pl][so];     os.y = szb[w][pl][so + 1];
            os.z = szb[w][pl][so + 2]; os.w = szb[w][pl][so + 3];
            *reinterpret_cast<float4*>(out_lv + (size_t)(pbase + pl) * N_STEPS + s0 + so) = ov;
            *reinterpret_cast<float4*>(out_sp + (size_t)(pbase + pl) * N_STEPS + s0 + so) = os;
        }
    }

    out_lq[pbase + l] = lsq;
}

extern "C" void kernel_launch(void* const* d_in, const int* in_sizes, int n_in,
                              void* d_out, int out_size)
{
    (void)in_sizes; (void)n_in; (void)out_size;
    // Phase 1 (fused): lambda nodes + cubic coefficients, one block per step
    node_kernel<<<N_STEPS, TPB1>>>(
        (const float*)d_in[2], (const float*)d_in[3],
        (const float*)d_in[4], (const float*)d_in[5],
        (const float*)d_in[6], (const float*)d_in[7]);
    // Phase 2: SDE sweep with piecewise-cubic lambda
    sde_kernel<<<N_PATHS / TPB2, TPB2>>>(
        (const float*)d_in[0], (const float*)d_in[1],
        (const float*)d_in[8],
        (float*)d_out);
}

// round 13
// speedup vs baseline: 1.3522x; 1.3522x over previous
#include <cuda_runtime.h>
#include <cstdint>

#define N_PATHS 65536
#define N_STEPS 512

// piecewise-cubic lambda table: 32 segments per step, 4 nodes per segment
#define NSEG    32
#define TILE    16

#define TPB1    128     // phase-1: one step per block, 2 threads per node-pair
#define TPB2    64
#define WARPS2  (TPB2/32)

// ---- constants (match reference float32 semantics) ----
#define DT_F        (1.0f/252.0f)
#define SQRT_DT_F   0.06299407883487120f     // sqrt(1/252)
#define KAPPA_F     2.72f
#define THETA_F     (-3.5f)
#define SIGMA_P_F   0.85f
#define RHO_F       (-0.85f)
#define CS_F        (0.5267826876426369f * 0.06299407883487120f) // sqrt(1-rho^2)*sqrt_dt
#define R_F         0.0373f
#define LAMBDA_MAX_F 3.0f
#define LOG_V_MIN_F (-7.0f)
#define LOG_V_MAX_F 2.0f
#define INV_NSTEPS  (1.0f/512.0f)
#define SEG_H       ((LOG_V_MAX_F - LOG_V_MIN_F) / (float)NSEG)      // 9/32
#define SEG_SCALE   ((float)NSEG / (LOG_V_MAX_F - LOG_V_MIN_F))      // 32/9
#define SEG_OFS     (-(LOG_V_MIN_F) * SEG_SCALE)
// drift restructure: lv + kappa*(theta-lv)*dt = A*lv + B
#define DRIFT_A     (1.0f - KAPPA_F * DT_F)
#define DRIFT_B     (KAPPA_F * THETA_F * DT_F)
#define NEG_SGDT    (-(SIGMA_P_F * DT_F))

// scratch (device global = legal scratch)
__device__ float4 g_coef[N_STEPS * NSEG];         // monomial cubic coeffs per segment

typedef unsigned long long ull;

// ---- packed f32x2 helpers (Blackwell fma.rn.f32x2) ----
__device__ __forceinline__ ull pack2(float a, float b) {
    ull r; asm("mov.b64 %0, {%1, %2};" : "=l"(r) : "f"(a), "f"(b)); return r;
}
__device__ __forceinline__ void unpack2(ull v, float& a, float& b) {
    asm("mov.b64 {%0, %1}, %2;" : "=f"(a), "=f"(b) : "l"(v));
}
__device__ __forceinline__ ull fma2(ull a, ull b, ull c) {
    ull d; asm("fma.rn.f32x2 %0, %1, %2, %3;" : "=l"(d) : "l"(a), "l"(b), "l"(c)); return d;
}
__device__ __forceinline__ ull mul2(ull a, ull b) {
    ull d; asm("mul.rn.f32x2 %0, %1, %2;" : "=l"(d) : "l"(a), "l"(b)); return d;
}

__device__ __forceinline__ float fast_tanh(float x) {
    float y;
    asm("tanh.approx.f32 %0, %1;" : "=f"(y) : "f"(x));
    return y;
}

// 5-op gelu on a pair (validated): gelu(x)=fma(0.5x, tanh(u), 0.5x)
__device__ __forceinline__ ull gelu2(ull x, ull GA, ull GB, ull GH) {
    ull x2 = mul2(x, x);
    ull u  = mul2(x, fma2(GA, x2, GB));
    ull hx = mul2(GH, x);
    float ulo, uhi; unpack2(u, ulo, uhi);
    ull tp = pack2(fast_tanh(ulo), fast_tanh(uhi));
    return fma2(hx, tp, hx);
}

// ============================================================================
// Phase 1 (fused, 2x parallel): lambda at segment nodes + cubic coefficients.
// One block = one time step, 128 threads. Thread t:
//   j = t>>2 (segment 0..31), p = (t>>1)&1 (node parity), half = t&1.
// Pair-MLP lanes = nodes u = p/3 and u = p/3 + 2/3 of segment j.
// Each half computes 4 of the 8 layer-2 groups; shfl_xor(1) reduces the two
// halves; shfl_xor(2) exchanges parity partners; t%4==0 emits the coeffs.
// ============================================================================
__global__ __launch_bounds__(TPB1, 4)
void node_kernel(const float* __restrict__ W1,  const float* __restrict__ b1,
                 const float* __restrict__ W2,  const float* __restrict__ b2,
                 const float* __restrict__ W3,  const float* __restrict__ b3)
{
    __shared__ float sw1t[32], sb1[32];
    __shared__ ull   sw0d[32], sb2d[32], sw3d[32];
    __shared__ __align__(16) float sW2[1024];
    __shared__ float sb3s;

    const int tid = threadIdx.x;
    for (int i = tid; i < 1024; i += TPB1) sW2[i] = W2[i];
    if (tid < 32) {
        float w0 = W1[2 * tid];
        sw0d[tid] = pack2(w0, w0);
        sw1t[tid] = W1[2 * tid + 1];
        sb1[tid]  = b1[tid];
        float bb = b2[tid];
        sb2d[tid] = pack2(bb, bb);
        float w3 = W3[tid];
        sw3d[tid] = pack2(w3, w3);
    }
    if (tid == 0) sb3s = b3[0];
    __syncthreads();

    const float4* W2v = reinterpret_cast<const float4*>(sW2);
    const ull GA = pack2(0.0356774081363059f, 0.0356774081363059f);
    const ull GB = pack2(0.7978845608028654f, 0.7978845608028654f);
    const ull GH = pack2(0.5f, 0.5f);

    const int s    = blockIdx.x;              // time step
    const int j    = tid >> 2;                // segment 0..31
    const int p    = (tid >> 1) & 1;          // node parity
    const int half = tid & 1;                 // group-half
    const float t = (float)s * INV_NSTEPS;

    // lane A: u = p/3 ; lane B: u = p/3 + 2/3  (of segment j)
    const float lvA = fmaf((float)j + (float)p * 0.3333333333f, SEG_H, LOG_V_MIN_F);
    const float lvB = lvA + 0.6666666666f * SEG_H;
    const ull lvp = pack2(lvA, lvB);

    ull h1[32];
    #pragma unroll
    for (int k = 0; k < 32; k++) {
        float c1 = fmaf(sw1t[k], t, sb1[k]);
        ull arg = fma2(sw0d[k], lvp, pack2(c1, c1));
        h1[k] = gelu2(arg, GA, GB, GH);
    }

    // this thread's 4 of 8 layer-2 groups
    ull red0 = pack2(0.0f, 0.0f);
    ull red1 = pack2(0.0f, 0.0f);
    #pragma unroll 1
    for (int jg = half * 4; jg < half * 4 + 4; jg++) {
        const int j0 = jg * 4;
        ull a0 = sb2d[j0 + 0];
        ull a1 = sb2d[j0 + 1];
        ull a2 = sb2d[j0 + 2];
        ull a3 = sb2d[j0 + 3];
        #pragma unroll
        for (int k4 = 0; k4 < 8; k4++) {
            ull h0 = h1[4 * k4 + 0];
            ull hA = h1[4 * k4 + 1];
            ull hB = h1[4 * k4 + 2];
            ull hC = h1[4 * k4 + 3];
            float4 q0 = W2v[(j0 + 0) * 8 + k4];
            float4 q1 = W2v[(j0 + 1) * 8 + k4];
            float4 q2 = W2v[(j0 + 2) * 8 + k4];
            float4 q3 = W2v[(j0 + 3) * 8 + k4];
            a0 = fma2(pack2(q0.x, q0.x), h0, a0);
            a0 = fma2(pack2(q0.y, q0.y), hA, a0);
            a0 = fma2(pack2(q0.z, q0.z), hB, a0);
            a0 = fma2(pack2(q0.w, q0.w), hC, a0);
            a1 = fma2(pack2(q1.x, q1.x), h0, a1);
            a1 = fma2(pack2(q1.y, q1.y), hA, a1);
            a1 = fma2(pack2(q1.z, q1.z), hB, a1);
            a1 = fma2(pack2(q1.w, q1.w), hC, a1);
            a2 = fma2(pack2(q2.x, q2.x), h0, a2);
            a2 = fma2(pack2(q2.y, q2.y), hA, a2);
            a2 = fma2(pack2(q2.z, q2.z), hB, a2);
            a2 = fma2(pack2(q2.w, q2.w), hC, a2);
            a3 = fma2(pack2(q3.x, q3.x), h0, a3);
            a3 = fma2(pack2(q3.y, q3.y), hA, a3);
            a3 = fma2(pack2(q3.z, q3.z), hB, a3);
            a3 = fma2(pack2(q3.w, q3.w), hC, a3);
        }
        red0 = fma2(sw3d[j0 + 0], gelu2(a0, GA, GB, GH), red0);
        red1 = fma2(sw3d[j0 + 1], gelu2(a1, GA, GB, GH), red1);
        red0 = fma2(sw3d[j0 + 2], gelu2(a2, GA, GB, GH), red0);
        red1 = fma2(sw3d[j0 + 3], gelu2(a3, GA, GB, GH), red1);
    }
    float rA0, rB0, rA1, rB1;
    unpack2(red0, rA0, rB0);
    unpack2(red1, rA1, rB1);
    float sumA = rA0 + rA1;
    float sumB = rB0 + rB1;
    // combine the two group-halves
    sumA += __shfl_xor_sync(0xffffffffu, sumA, 1);
    sumB += __shfl_xor_sync(0xffffffffu, sumB, 1);
    float lamA = LAMBDA_MAX_F * tanhf(sumA + sb3s);   // u = p/3
    float lamB = LAMBDA_MAX_F * tanhf(sumB + sb3s);   // u = p/3 + 2/3

    // exchange with parity partner (lane ^ 2): get u = 1/3 and u = 1
    float oA = __shfl_xor_sync(0xffffffffu, lamA, 2);
    float oB = __shfl_xor_sync(0xffffffffu, lamB, 2);
    if ((tid & 3) == 0) {
        float f0 = lamA, f2 = lamB;   // own: u = 0, 2/3
        float f1 = oA,   f3 = oB;     // partner: u = 1/3, 1
        float4 c;
        c.x = f0;
        c.y = 0.5f * (-11.0f * f0 + 18.0f * f1 - 9.0f  * f2 + 2.0f * f3);
        c.z = 0.5f * ( 18.0f * f0 - 45.0f * f1 + 36.0f * f2 - 9.0f * f3);
        c.w = 0.5f * ( -9.0f * f0 + 27.0f * f1 - 27.0f * f2 + 9.0f * f3);
        g_coef[s * NSEG + j] = c;
    }
}

// ============================================================================
// Phase 2: SDE sweep (R11 skeleton). Register double-buffering for BOTH z and
// the coefficient tile: next tile's coef LDGs are issued alongside the z
// prefetch and held in registers across the step loop, then STS'd at the next
// tile top. No cp.async (regressed in R12); no exposed refill latency.
// ============================================================================
__global__ __launch_bounds__(TPB2, 8)
void sde_kernel(const float* __restrict__ z1, const float* __restrict__ z2,
                const float* __restrict__ init_log_v,
                float* __restrict__ out)
{
    __shared__ float sza[WARPS2][32][TILE + 1];   // z1 in -> log_v out
    __shared__ float szb[WARPS2][32][TILE + 1];   // z2 in -> spot  out
    __shared__ __align__(16) float4 scoef[TILE][NSEG];   // 8 KB coeff tile

    const int tid = threadIdx.x;
    const int w = tid >> 5;
    const int l = tid & 31;
    const int pbase = blockIdx.x * TPB2 + w * 32;

    const float* z1w = z1 + (size_t)pbase * N_STEPS;
    const float* z2w = z2 + (size_t)pbase * N_STEPS;
    float* out_lv = out;
    float* out_sp = out + (size_t)N_PATHS * N_STEPS;
    float* out_lq = out + 2 * (size_t)N_PATHS * N_STEPS;

    float lv  = init_log_v[0];
    float ls  = 0.0f;
    float lsq = 0.0f;

    const int pl_lo = (l >> 2);        // 0..7
    const int so    = (l & 3) * 4;     // 0,4,8,12

    // ---- initial prefetch (tile 0): z and coef into registers ----
    float4 r1[4], r2[4], cpref[8];
    #pragma unroll
    for (int it = 0; it < 4; it++) {
        int pl = it * 8 + pl_lo;
        r1[it] = *reinterpret_cast<const float4*>(z1w + (size_t)pl * N_STEPS + so);
        r2[it] = *reinterpret_cast<const float4*>(z2w + (size_t)pl * N_STEPS + so);
    }
    #pragma unroll
    for (int i = 0; i < 8; i++)
        cpref[i] = g_coef[tid + i * TPB2];

    #pragma unroll 1
    for (int s0 = 0; s0 < N_STEPS; s0 += TILE) {
        __syncthreads();   // previous tile's smem reads complete

        // ---- deposit prefetched z into padded smem ----
        #pragma unroll
        for (int it = 0; it < 4; it++) {
            int pl = it * 8 + pl_lo;
            sza[w][pl][so]     = r1[it].x; sza[w][pl][so + 1] = r1[it].y;
            sza[w][pl][so + 2] = r1[it].z; sza[w][pl][so + 3] = r1[it].w;
            szb[w][pl][so]     = r2[it].x; szb[w][pl][so + 1] = r2[it].y;
            szb[w][pl][so + 2] = r2[it].z; szb[w][pl][so + 3] = r2[it].w;
        }
        // ---- deposit prefetched coef tile into smem ----
        {
            float4* dst = &scoef[0][0];
            #pragma unroll
            for (int i = 0; i < 8; i++)
                dst[tid + i * TPB2] = cpref[i];
        }

        // ---- issue NEXT tile's loads (latency hidden under step loop) ----
        if (s0 + TILE < N_STEPS) {
            #pragma unroll
            for (int it = 0; it < 4; it++) {
                int pl = it * 8 + pl_lo;
                r1[it] = *reinterpret_cast<const float4*>(z1w + (size_t)pl * N_STEPS + s0 + TILE + so);
                r2[it] = *reinterpret_cast<const float4*>(z2w + (size_t)pl * N_STEPS + s0 + TILE + so);
            }
            const float4* src = g_coef + (size_t)(s0 + TILE) * NSEG;
            #pragma unroll
            for (int i = 0; i < 8; i++)
                cpref[i] = src[tid + i * TPB2];
        }
        __syncthreads();   // z + coef tiles visible to all

        // ---- 16 sequential SDE steps (fully unrolled) ----
        #pragma unroll
        for (int si = 0; si < TILE; si++) {
            // off-chain pieces (z known at tile start)
            float z1s = sza[w][l][si];
            float z2s = szb[w][l][si];
            float dwv = SQRT_DT_F * z1s;
            float dws = fmaf(RHO_F, dwv, CS_F * z2s);
            float e    = fmaf(SIGMA_P_F, dwv, DRIFT_B);
            float base = fmaf(DRIFT_A, lv, e);

            // lambda chain: fma -> F2I.RD -> clamp -> LDS.128 -> Horner
            float x  = fmaf(lv, SEG_SCALE, SEG_OFS);      // [0, 32]
            int   j  = __float2int_rd(x);
            j = max(min(j, NSEG - 1), 0);
            float u  = x - (float)j;
            float4 c = scoef[si][j];
            float lam = fmaf(fmaf(fmaf(c.w, u, c.z), u, c.y), u, c.x);

            float lv_next = fmaf(lam, NEG_SGDT, base);
            lv_next = fminf(fmaxf(lv_next, LOG_V_MIN_F), LOG_V_MAX_F);

            // lv >= -7 => exp(lv) >= 9e-4 >> 1e-10: vol = exp(lv/2), ev = vol^2
            float vol = __expf(0.5f * lv);
            float ev  = vol * vol;
            float ls_next = fmaf(vol, dws, fmaf(ev, -0.5f * DT_F, ls + R_F * DT_F));

            lsq = fmaf(lam * lam, DT_F, lsq);

            sza[w][l][si] = lv_next;
            szb[w][l][si] = __expf(ls_next);

            lv = lv_next;
            ls = ls_next;
        }
        __syncwarp();   // own-warp sza/szb writes visible before flush

        // ---- flush outputs (padded smem -> coalesced STG.128) ----
        #pragma unroll
        for (int it = 0; it < 4; it++) {
            int pl = it * 8 + pl_lo;
            float4 ov, os;
            ov.x = sza[w][pl][so];     ov.y = sza[w][pl][so + 1];
            ov.z = sza[w][pl][so + 2]; ov.w = sza[w][pl][so + 3];
            os.x = szb[w][pl][so];     os.y = szb[w][pl][so + 1];
            os.z = szb[w][pl][so + 2]; os.w = szb[w][pl][so + 3];
            *reinterpret_cast<float4*>(out_lv + (size_t)(pbase + pl) * N_STEPS + s0 + so) = ov;
            *reinterpret_cast<float4*>(out_sp + (size_t)(pbase + pl) * N_STEPS + s0 + so) = os;
        }
    }

    out_lq[pbase + l] = lsq;
}

extern "C" void kernel_launch(void* const* d_in, const int* in_sizes, int n_in,
                              void* d_out, int out_size)
{
    (void)in_sizes; (void)n_in; (void)out_size;
    // Phase 1 (fused): lambda nodes + cubic coefficients, one block per step
    node_kernel<<<N_STEPS, TPB1>>>(
        (const float*)d_in[2], (const float*)d_in[3],
        (const float*)d_in[4], (const float*)d_in[5],
        (const float*)d_in[6], (const float*)d_in[7]);
    // Phase 2: SDE sweep with piecewise-cubic lambda
    sde_kernel<<<N_PATHS / TPB2, TPB2>>>(
        (const float*)d_in[0], (const float*)d_in[1],
        (const float*)d_in[8],
        (float*)d_out);
}